// round 16
// baseline (speedup 1.0000x reference)
#include <cuda_runtime.h>
#include <cuda_bf16.h>
#include <cuda_fp16.h>
#include <math.h>
#include <stdint.h>

#define BB 64
#define SS 50
#define EE 512
#define HH 1024
#define VTS 32000
#define NSTEP 49
#define MPROJ (NSTEP*BB)
#define MPAD  3200
#define G4H 4096
#define KSPLIT 8           /* fallback path split */
#define KCHUNK 128
#define KA 1024
#define DCTA 128           /* persistent decoder grid (single wave) */
#define DKS 4              /* persistent decoder k-splits */
#define DKC 256            /* K per decoder CTA */

typedef unsigned long long ull;

__device__ __forceinline__ ull dup2(float x){
    ull r; asm("mov.b64 %0, {%1, %1};" : "=l"(r) : "f"(x)); return r;
}
__device__ __forceinline__ void ffma2(ull &d, ull a, ull b){
    asm("fma.rn.f32x2 %0, %1, %2, %0;" : "+l"(d) : "l"(a), "l"(b));
}
__device__ __forceinline__ float2 unpk(ull v){
    float2 f; asm("mov.b64 {%0, %1}, %2;" : "=f"(f.x), "=f"(f.y) : "l"(v)); return f;
}
__device__ __forceinline__ uint32_t smem_u32(const void* p){
    uint32_t a;
    asm("{ .reg .u64 t; cvta.to.shared.u64 t, %1; cvt.u32.u64 %0, t; }" : "=r"(a) : "l"(p));
    return a;
}
__device__ __forceinline__ void cpasync16(uint32_t dst, const void* src){
    asm volatile("cp.async.cg.shared.global [%0], [%1], 16;" :: "r"(dst), "l"(src));
}
__device__ __forceinline__ void cp_commit(){
    asm volatile("cp.async.commit_group;");
}
__device__ __forceinline__ void ldm4(uint32_t* r, uint32_t a){
    asm volatile("ldmatrix.sync.aligned.m8n8.x4.shared.b16 {%0,%1,%2,%3}, [%4];"
        : "=r"(r[0]), "=r"(r[1]), "=r"(r[2]), "=r"(r[3]) : "r"(a));
}
__device__ __forceinline__ void mma16816h(float* c, const uint32_t* a, uint32_t b0, uint32_t b1){
    asm volatile("mma.sync.aligned.m16n8k16.row.col.f32.f16.f16.f32 "
        "{%0,%1,%2,%3}, {%4,%5,%6,%7}, {%8,%9}, {%0,%1,%2,%3};"
        : "+f"(c[0]), "+f"(c[1]), "+f"(c[2]), "+f"(c[3])
        : "r"(a[0]), "r"(a[1]), "r"(a[2]), "r"(a[3]), "r"(b0), "r"(b1));
}
__device__ __forceinline__ ull pack4h(float x, float y, float z, float w){
    __half h0 = __float2half_rn(x), h1 = __float2half_rn(y);
    __half h2 = __float2half_rn(z), h3 = __float2half_rn(w);
    ull p;
    asm("mov.b64 %0, {%1,%2,%3,%4};" : "=l"(p)
        : "h"(*(unsigned short*)&h0), "h"(*(unsigned short*)&h1),
          "h"(*(unsigned short*)&h2), "h"(*(unsigned short*)&h3));
    return p;
}
__device__ __forceinline__ int ld_acq(const int* p){
    int v; asm volatile("ld.global.acquire.gpu.b32 %0, [%1];" : "=r"(v) : "l"(p) : "memory");
    return v;
}
__device__ __forceinline__ void st_rlx(int* p, int v){
    asm volatile("st.global.relaxed.gpu.b32 [%0], %1;" :: "l"(p), "r"(v) : "memory");
}

__device__ float g_enc_out[BB*SS*EE];
__device__ float g_avg[BB*EE];
__device__ float g_ctx[BB*EE];
__device__ float g_h[BB*HH];
__device__ float g_c[BB*HH];
__device__ float g_part[KSPLIT*BB*G4H];
__device__ float g_pre[MPAD*G4H];
__device__ __half g_h16[BB*HH];
__device__ __half g_Ah[(size_t)MPAD*KA];
__device__ __half g_Bh[(size_t)VTS*KA];
__device__ __half g_Apre[(size_t)MPAD*KA];    // reused: enc A first, then pre A
__device__ __half g_Wih16[(size_t)G4H*KA];
__device__ __half g_Whh16[(size_t)G4H*KA];
__device__ __half g_CatW16[(size_t)EE*KA];

// distributed barrier flags (monotonic counters; all equal between launches)
__device__ int g_arr[DCTA];

// ============================================================
// fp16 A rows for encoder GEMM: row r = [enc_emb[src[r]] | pos_emb[pos[r]]]
// ============================================================
__global__ __launch_bounds__(256)
void build_aenc(const int* __restrict__ src, const int* __restrict__ pos,
                const float* __restrict__ enc_emb, const float* __restrict__ pos_emb)
{
    int r = blockIdx.x;
    int c = threadIdx.x * 4;
    const float* srcp;
    if (c < 512) srcp = enc_emb + (size_t)src[r]*512 + c;
    else         srcp = pos_emb + (size_t)pos[r]*512 + (c - 512);
    float4 v = *(const float4*)srcp;
    *(ull*)(g_Apre + (size_t)r*KA + c) = pack4h(v.x, v.y, v.z, v.w);
}

__global__ __launch_bounds__(256)
void conv_catw(const float* __restrict__ W)
{
    size_t i = (size_t)blockIdx.x*blockDim.x + threadIdx.x;
    float4 v = ((const float4*)W)[i];
    *(ull*)(g_CatW16 + i*4) = pack4h(v.x, v.y, v.z, v.w);
}

__global__ void avg_kernel()
{
    int b = blockIdx.x, e = threadIdx.x;
    float s = 0.f;
    #pragma unroll 5
    for (int si=0; si<SS; si++) s += g_enc_out[(b*SS+si)*EE + e];
    g_avg[b*EE + e] = s * (1.0f/50.0f);
}

__global__ __launch_bounds__(256)
void h0_kernel(const float* __restrict__ scale_W, const float* __restrict__ scale_b)
{
    int gw = blockIdx.x*8 + (threadIdx.x >> 5);
    int lane = threadIdx.x & 31;
    int b = gw >> 10, h = gw & 1023;
    const float* a = g_avg + b*EE;
    const float* w = scale_W + (size_t)h*EE;
    float s = 0.f;
    #pragma unroll
    for (int k = 0; k < 16; k++){
        int idx = k*32 + lane;
        s += a[idx] * w[idx];
    }
    #pragma unroll
    for (int o=16;o>0;o>>=1) s += __shfl_xor_sync(0xffffffffu, s, o);
    if (lane == 0){
        float v = fmaxf(s + scale_b[h], 0.f);
        g_h[b*HH + h] = v;
        g_c[b*HH + h] = v;
        g_h16[b*HH + h] = __float2half_rn(v);
    }
}

__global__ void attn_kernel(const float* __restrict__ attn_W, const int* __restrict__ src)
{
    int b = blockIdx.x, tid = threadIdx.x;
    __shared__ float sc[56];
    __shared__ float aw[56];
    int w = tid >> 5, lane = tid & 31;
    for (int s = w; s < SS; s += 8){
        const float* row = g_enc_out + (size_t)(b*SS+s)*EE;
        float a = 0.f;
        for (int e = lane; e < EE; e += 32) a += row[e]*attn_W[e];
        #pragma unroll
        for (int o=16;o>0;o>>=1) a += __shfl_xor_sync(0xffffffffu, a, o);
        if (lane==0) sc[s] = a;
    }
    __syncthreads();
    if (tid == 0){
        float mx = -1e30f;
        for (int s=0;s<SS;s++) mx = fmaxf(mx, sc[s]);
        float tot = 0.f;
        for (int s=0;s<SS;s++){
            float e = (src[b*SS+s]==0) ? 0.f : expf(sc[s]-mx);
            aw[s] = e; tot += e;
        }
        float inv = 1.f/tot;
        for (int s=0;s<SS;s++) aw[s] *= inv;
    }
    __syncthreads();
    for (int e = tid; e < EE; e += blockDim.x){
        float a = 0.f;
        #pragma unroll 5
        for (int s=0;s<SS;s++) a += aw[s]*g_enc_out[(size_t)(b*SS+s)*EE + e];
        g_ctx[b*EE + e] = a;
    }
}

__global__ __launch_bounds__(256)
void build_apre(const int* __restrict__ tgt, const float* __restrict__ dec_emb)
{
    int r = blockIdx.x;
    int b = r & 63, t = r >> 6;
    int c = threadIdx.x * 4;
    const float* srcp;
    if (c < 512){
        int tok = tgt[b*50 + t];
        srcp = dec_emb + (size_t)tok*512 + c;
    } else {
        srcp = g_ctx + b*EE + (c - 512);
    }
    float4 v = *(const float4*)srcp;
    *(ull*)(g_Apre + (size_t)r*KA + c) = pack4h(v.x, v.y, v.z, v.w);
}

__global__ __launch_bounds__(256)
void conv_wih(const float* __restrict__ W)
{
    size_t i = (size_t)blockIdx.x*blockDim.x + threadIdx.x;
    float4 v = ((const float4*)W)[i];
    *(ull*)(g_Wih16 + i*4) = pack4h(v.x, v.y, v.z, v.w);
}
__global__ __launch_bounds__(256)
void conv_whh(const float* __restrict__ W)
{
    size_t i = (size_t)blockIdx.x*blockDim.x + threadIdx.x;
    float4 v = ((const float4*)W)[i];
    *(ull*)(g_Whh16 + i*4) = pack4h(v.x, v.y, v.z, v.w);
}
__global__ __launch_bounds__(256)
void conv_w(const float* __restrict__ W)
{
    size_t i = (size_t)blockIdx.x*blockDim.x + threadIdx.x;
    float4 v = ((const float4*)W)[i];
    *(ull*)(g_Bh + i*4) = pack4h(v.x, v.y, v.z, v.w);
}

#define NSTG 4
#define TSTA 10240
#define TSTB 20480
#define SM_PROJ (NSTG*(TSTA+TSTB))
#define NKS (KA/32)

// ---- encoder GEMM: g_enc_out = A_enc . CatW^T + cat_b
__global__ __launch_bounds__(256)
void enc_mma(const float* __restrict__ bias)
{
    extern __shared__ __align__(16) char sm[];
    const uint32_t uA = smem_u32(sm);
    const uint32_t uB = uA + NSTG*TSTA;
    const int tid = threadIdx.x;
    const int wid = tid >> 5, lane = tid & 31;
    const int m0 = blockIdx.x * 128;
    const int n0 = blockIdx.y * 256;
    const int wm = wid & 3, wn = wid >> 2;

    float acc[2][16][4];
    #pragma unroll
    for (int a=0;a<2;a++)
        #pragma unroll
        for (int j=0;j<16;j++)
            #pragma unroll
            for (int x=0;x<4;x++) acc[a][j][x] = 0.f;

    const __half* gA = g_Apre + (size_t)m0*KA;
    const __half* gB = g_CatW16 + (size_t)n0*KA;

    auto load_stage = [&](int slot, int ks){
        int k0 = ks * 32;
        uint32_t sA = uA + slot*TSTA;
        uint32_t sB = uB + slot*TSTB;
        #pragma unroll
        for (int i = 0; i < 2; i++){
            int idx = tid + 256*i;
            int row = idx >> 2, lc = idx & 3;
            cpasync16(sA + row*80 + lc*16, gA + (size_t)row*KA + k0 + lc*8);
        }
        #pragma unroll
        for (int i = 0; i < 4; i++){
            int idx = tid + 256*i;
            int row = idx >> 2, lc = idx & 3;
            cpasync16(sB + row*80 + lc*16, gB + (size_t)row*KA + k0 + lc*8);
        }
        cp_commit();
    };

    load_stage(0, 0); load_stage(1, 1); load_stage(2, 2);

    const int g  = lane >> 3;
    const int lr = lane & 7;

    for (int ks = 0; ks < NKS; ks++){
        asm volatile("cp.async.wait_group 2;");
        __syncthreads();
        int ld = ks + NSTG - 1;
        if (ld < NKS) load_stage(ld & (NSTG-1), ld);
        else cp_commit();

        const uint32_t bufA = uA + (ks & (NSTG-1))*TSTA;
        const uint32_t bufB = uB + (ks & (NSTG-1))*TSTB;

        #pragma unroll
        for (int kk = 0; kk < 32; kk += 16){
            uint32_t afr[2][4];
            #pragma unroll
            for (int mi = 0; mi < 2; mi++){
                int row = wm*32 + mi*16 + ((g & 1) ? 8 : 0) + lr;
                int kof = kk + (g >> 1)*8;
                ldm4(afr[mi], bufA + row*80 + kof*2);
            }
            uint32_t bfr[8][4];
            #pragma unroll
            for (int p = 0; p < 8; p++){
                int row = wn*128 + p*16 + (g >> 1)*8 + lr;
                int kof = kk + (g & 1)*8;
                ldm4(bfr[p], bufB + row*80 + kof*2);
            }
            #pragma unroll
            for (int mi = 0; mi < 2; mi++)
                #pragma unroll
                for (int j = 0; j < 16; j++){
                    int p = j >> 1, h2 = (j & 1)*2;
                    mma16816h(acc[mi][j], afr[mi], bfr[p][h2], bfr[p][h2+1]);
                }
        }
        __syncthreads();
    }

    const int tm = lane >> 2;
    const int tn = (lane & 3)*2;
    #pragma unroll
    for (int mi = 0; mi < 2; mi++){
        #pragma unroll
        for (int j = 0; j < 16; j++){
            int gn = n0 + wn*128 + j*8 + tn;
            float2 bb = *(const float2*)(bias + gn);
            int gm0 = m0 + wm*32 + mi*16 + tm;
            {
                float2 o; o.x = acc[mi][j][0] + bb.x; o.y = acc[mi][j][1] + bb.y;
                *(float2*)(g_enc_out + (size_t)gm0*EE + gn) = o;
            }
            int gm1 = gm0 + 8;
            {
                float2 o; o.x = acc[mi][j][2] + bb.x; o.y = acc[mi][j][3] + bb.y;
                *(float2*)(g_enc_out + (size_t)gm1*EE + gn) = o;
            }
        }
    }
}

// ---- pre-GEMM: g_pre = A_pre . W_ih^T + b_ih + b_hh
__global__ __launch_bounds__(256)
void pre_mma(const float* __restrict__ b_ih, const float* __restrict__ b_hh)
{
    extern __shared__ __align__(16) char sm[];
    const uint32_t uA = smem_u32(sm);
    const uint32_t uB = uA + NSTG*TSTA;
    const int tid = threadIdx.x;
    const int wid = tid >> 5, lane = tid & 31;
    const int m0 = blockIdx.x * 128;
    const int n0 = blockIdx.y * 256;
    const int wm = wid & 3, wn = wid >> 2;

    float acc[2][16][4];
    #pragma unroll
    for (int a=0;a<2;a++)
        #pragma unroll
        for (int j=0;j<16;j++)
            #pragma unroll
            for (int x=0;x<4;x++) acc[a][j][x] = 0.f;

    const __half* gA = g_Apre + (size_t)m0*KA;
    const __half* gB = g_Wih16 + (size_t)n0*KA;

    auto load_stage = [&](int slot, int ks){
        int k0 = ks * 32;
        uint32_t sA = uA + slot*TSTA;
        uint32_t sB = uB + slot*TSTB;
        #pragma unroll
        for (int i = 0; i < 2; i++){
            int idx = tid + 256*i;
            int row = idx >> 2, lc = idx & 3;
            cpasync16(sA + row*80 + lc*16, gA + (size_t)row*KA + k0 + lc*8);
        }
        #pragma unroll
        for (int i = 0; i < 4; i++){
            int idx = tid + 256*i;
            int row = idx >> 2, lc = idx & 3;
            cpasync16(sB + row*80 + lc*16, gB + (size_t)row*KA + k0 + lc*8);
        }
        cp_commit();
    };

    load_stage(0, 0); load_stage(1, 1); load_stage(2, 2);

    const int g  = lane >> 3;
    const int lr = lane & 7;

    for (int ks = 0; ks < NKS; ks++){
        asm volatile("cp.async.wait_group 2;");
        __syncthreads();
        int ld = ks + NSTG - 1;
        if (ld < NKS) load_stage(ld & (NSTG-1), ld);
        else cp_commit();

        const uint32_t bufA = uA + (ks & (NSTG-1))*TSTA;
        const uint32_t bufB = uB + (ks & (NSTG-1))*TSTB;

        #pragma unroll
        for (int kk = 0; kk < 32; kk += 16){
            uint32_t afr[2][4];
            #pragma unroll
            for (int mi = 0; mi < 2; mi++){
                int row = wm*32 + mi*16 + ((g & 1) ? 8 : 0) + lr;
                int kof = kk + (g >> 1)*8;
                ldm4(afr[mi], bufA + row*80 + kof*2);
            }
            uint32_t bfr[8][4];
            #pragma unroll
            for (int p = 0; p < 8; p++){
                int row = wn*128 + p*16 + (g >> 1)*8 + lr;
                int kof = kk + (g & 1)*8;
                ldm4(bfr[p], bufB + row*80 + kof*2);
            }
            #pragma unroll
            for (int mi = 0; mi < 2; mi++)
                #pragma unroll
                for (int j = 0; j < 16; j++){
                    int p = j >> 1, h2 = (j & 1)*2;
                    mma16816h(acc[mi][j], afr[mi], bfr[p][h2], bfr[p][h2+1]);
                }
        }
        __syncthreads();
    }

    const int tm = lane >> 2;
    const int tn = (lane & 3)*2;
    #pragma unroll
    for (int mi = 0; mi < 2; mi++){
        #pragma unroll
        for (int j = 0; j < 16; j++){
            int gn = n0 + wn*128 + j*8 + tn;
            float2 bi = *(const float2*)(b_ih + gn);
            float2 bh = *(const float2*)(b_hh + gn);
            float bx = bi.x + bh.x, by = bi.y + bh.y;
            int gm0 = m0 + wm*32 + mi*16 + tm;
            {
                float2 o; o.x = acc[mi][j][0] + bx; o.y = acc[mi][j][1] + by;
                *(float2*)(g_pre + (size_t)gm0*G4H + gn) = o;
            }
            int gm1 = gm0 + 8;
            {
                float2 o; o.x = acc[mi][j][2] + bx; o.y = acc[mi][j][3] + by;
                *(float2*)(g_pre + (size_t)gm1*G4H + gn) = o;
            }
        }
    }
}

// ============================================================
// PERSISTENT tensor-core decoder with distributed flag barrier.
// ============================================================
#define DPITCH 528
#define DSM_AS 0
#define DSM_BS (64*DPITCH)
#define DSM_TOT (DSM_BS + 128*DPITCH)

__global__ __launch_bounds__(128)
void decoder_tc(void)
{
    extern __shared__ __align__(16) char dsm[];
    const uint32_t uAs = smem_u32(dsm) + DSM_AS;
    const uint32_t uBs = smem_u32(dsm) + DSM_BS;
    const int cid = blockIdx.x;
    const int ntile = cid & 31;
    const int ksplit = cid >> 5;
    const int n0 = ntile * 128;
    const int kbase = ksplit * DKC;
    const int tid = threadIdx.x;
    const int wid = tid >> 5, lane = tid & 31;

    // distributed barrier base (all slots equal between launches)
    const int bbase = g_arr[cid];
    int barix = 0;

    #pragma unroll
    for (int l = 0; l < 32; l++){
        int idx = tid + 128*l;
        int n = idx >> 5, kc = (idx & 31)*8;
        uint4 v = *(const uint4*)(g_Whh16 + (size_t)(n0+n)*KA + kbase + kc);
        *(uint4*)(dsm + DSM_BS + n*DPITCH + kc*2) = v;
    }

    const int gidb = cid*128 + tid;
    float creg[4];
    #pragma unroll
    for (int e = 0; e < 4; e++) creg[e] = g_c[gidb + e*16384];

    const int g  = lane >> 3;
    const int lr = lane & 7;
    const int tm = lane >> 2;
    const int tn = (lane & 3)*2;

    for (int t = 0; t < NSTEP; t++){
        #pragma unroll
        for (int l = 0; l < 16; l++){
            int idx = tid + 128*l;
            int m = idx >> 5, kc = (idx & 31)*8;
            uint4 v = __ldcg((const uint4*)(g_h16 + m*HH + kbase + kc));
            *(uint4*)(dsm + DSM_AS + m*DPITCH + kc*2) = v;
        }
        __syncthreads();

        float acc[16][4];
        #pragma unroll
        for (int j=0;j<16;j++)
            #pragma unroll
            for (int x=0;x<4;x++) acc[j][x] = 0.f;

        #pragma unroll
        for (int kk = 0; kk < DKC; kk += 16){
            uint32_t afr[4];
            {
                int row = wid*16 + ((g & 1) ? 8 : 0) + lr;
                int kof = kk + (g >> 1)*8;
                ldm4(afr, uAs + row*DPITCH + kof*2);
            }
            uint32_t bfr[8][4];
            #pragma unroll
            for (int p = 0; p < 8; p++){
                int row = p*16 + (g >> 1)*8 + lr;
                int kof = kk + (g & 1)*8;
                ldm4(bfr[p], uBs + row*DPITCH + kof*2);
            }
            #pragma unroll
            for (int j = 0; j < 16; j++){
                int p = j >> 1, h2 = (j & 1)*2;
                mma16816h(acc[j], afr, bfr[p][h2], bfr[p][h2+1]);
            }
        }

        {
            float* outp = g_part + (size_t)ksplit*(BB*G4H);
            #pragma unroll
            for (int j = 0; j < 16; j++){
                int n = n0 + j*8 + tn;
                int m0r = wid*16 + tm;
                *(float2*)(outp + (size_t)m0r*G4H + n) =
                    make_float2(acc[j][0], acc[j][1]);
                *(float2*)(outp + (size_t)(m0r+8)*G4H + n) =
                    make_float2(acc[j][2], acc[j][3]);
            }
        }
        // ---- distributed barrier #1 (partials visible)
        barix++;
        __syncthreads();
        if (tid == 0){ __threadfence(); st_rlx(&g_arr[cid], bbase + barix); }
        {
            int tgt = bbase + barix;
            while (ld_acq(&g_arr[tid]) - tgt < 0) { }
        }
        __syncthreads();

        #pragma unroll
        for (int e = 0; e < 4; e++){
            int gid = gidb + e*16384;
            int b = gid >> 10, h = gid & 1023;
            size_t prow = (size_t)(t*64 + b)*G4H;
            float gi = g_pre[prow + h];
            float gf = g_pre[prow + 1024 + h];
            float gg = g_pre[prow + 2048 + h];
            float go = g_pre[prow + 3072 + h];
            int base = b*G4H;
            #pragma unroll
            for (int s=0;s<DKS;s++){
                const float* p = g_part + (size_t)s*(BB*G4H) + base;
                gi += __ldcg(p + h);
                gf += __ldcg(p + 1024 + h);
                gg += __ldcg(p + 2048 + h);
                go += __ldcg(p + 3072 + h);
            }
            float c = creg[e];
            float ii = 1.f/(1.f+expf(-gi));
            float ff = 1.f/(1.f+expf(-gf));
            float oo = 1.f/(1.f+expf(-go));
            float gt = tanhf(gg);
            float cn = ff*c + ii*gt;
            float hn = oo*tanhf(cn);
            creg[e] = cn;
            __half hh = __float2half_rn(hn);
            g_h16[gid] = hh;
            g_Ah[(size_t)(t*64 + b)*KA + h] = hh;
        }
        // ---- distributed barrier #2 (h visible)
        barix++;
        __syncthreads();
        if (tid == 0){ __threadfence(); st_rlx(&g_arr[cid], bbase + barix); }
        {
            int tgt = bbase + barix;
            while (ld_acq(&g_arr[tid]) - tgt < 0) { }
        }
        __syncthreads();
    }
}

// ============================================================
// Fallback per-step kernels (fp32 path)
// ============================================================
__global__ __launch_bounds__(128)
void gates_gemm(const float* __restrict__ W_hh)
{
    __shared__ __align__(16) float As[64*20];
    __shared__ __align__(16) float Bs[16*132];
    const int n0 = blockIdx.x * 128;
    const int kbase = blockIdx.y * KCHUNK;
    const int tid = threadIdx.x;
    const int tx = tid & 15, ty = tid >> 4;

    ull acc[8][2][2];
    #pragma unroll
    for (int i=0;i<8;i++)
        #pragma unroll
        for (int q=0;q<2;q++){ acc[i][q][0]=0ull; acc[i][q][1]=0ull; }

    for (int kt = 0; kt < KCHUNK; kt += 16){
        const int kg0 = kbase + kt;
        #pragma unroll
        for (int l=0;l<2;l++){
            int f4 = tid + 128*l;
            int row = f4 >> 2, k4 = (f4 & 3) << 2;
            float4 v = *(const float4*)(g_h + row*1024 + kg0 + k4);
            *(float4*)(As + row*20 + k4) = v;
        }
        #pragma unroll
        for (int l=0;l<4;l++){
            int f4 = tid + 128*l;
            int row = f4 >> 2, k4 = (f4 & 3) << 2;
            float4 v = *(const float4*)(W_hh + (size_t)(n0+row)*1024 + kg0 + k4);
            Bs[(k4+0)*132 + row] = v.x;
            Bs[(k4+1)*132 + row] = v.y;
            Bs[(k4+2)*132 + row] = v.z;
            Bs[(k4+3)*132 + row] = v.w;
        }
        __syncthreads();
        #pragma unroll
        for (int kq=0;kq<4;kq++){
            float4 av[8];
            #pragma unroll
            for (int i=0;i<8;i++) av[i] = *(const float4*)(As + (ty*8+i)*20 + kq*4);
            #pragma unroll
            for (int kk=0;kk<4;kk++){
                ull a2[8];
                #pragma unroll
                for (int i=0;i<8;i++){
                    float a = (kk==0)?av[i].x:(kk==1)?av[i].y:(kk==2)?av[i].z:av[i].w;
                    a2[i] = dup2(a);
                }
                const int k = kq*4+kk;
                #pragma unroll
                for (int q=0;q<2;q++){
                    ulonglong2 bv = *(const ulonglong2*)(Bs + k*132 + tx*4 + q*64);
                    #pragma unroll
                    for (int i=0;i<8;i++){ ffma2(acc[i][q][0], a2[i], bv.x);
                                           ffma2(acc[i][q][1], a2[i], bv.y); }
                }
            }
        }
        __syncthreads();
    }
    float* outp = g_part + (size_t)blockIdx.y*(BB*G4H);
    #pragma unroll
    for (int i=0;i<8;i++){
        int m = ty*8 + i;
        #pragma unroll
        for (int q=0;q<2;q++){
            int n = n0 + tx*4 + q*64;
            float2 p0 = unpk(acc[i][q][0]);
            float2 p1 = unpk(acc[i][q][1]);
            *(float4*)(outp + (size_t)m*G4H + n) = make_float4(p0.x, p0.y, p1.x, p1.y);
        }
    }
}

__global__ void lstm_pw(int t)
{
    int gid = blockIdx.x*blockDim.x + threadIdx.x;
    int b = gid >> 10, h = gid & 1023;
    size_t prow = (size_t)(t*64 + b)*G4H;
    float gi = g_pre[prow + h];
    float gf = g_pre[prow + 1024 + h];
    float gg = g_pre[prow + 2048 + h];
    float go = g_pre[prow + 3072 + h];
    int base = b*G4H;
    #pragma unroll
    for (int s=0;s<KSPLIT;s++){
        const float* p = g_part + (size_t)s*(BB*G4H) + base;
        gi += p[h]; gf += p[1024+h]; gg += p[2048+h]; go += p[3072+h];
    }
    float c  = g_c[gid];
    float ii = 1.f/(1.f+expf(-gi));
    float ff = 1.f/(1.f+expf(-gf));
    float oo = 1.f/(1.f+expf(-go));
    float gt = tanhf(gg);
    float cn = ff*c + ii*gt;
    float hn = oo*tanhf(cn);
    g_c[gid] = cn; g_h[gid] = hn;
    g_Ah[(size_t)(t*64 + b)*KA + h] = __float2half_rn(hn);
}

// ============================================================
// Projection via mma.sync fp16
// ============================================================
__global__ __launch_bounds__(256)
void proj_mma(float* __restrict__ out, const float* __restrict__ bias)
{
    extern __shared__ __align__(16) char sm[];
    const uint32_t uA = smem_u32(sm);
    const uint32_t uB = uA + NSTG*TSTA;
    const int tid = threadIdx.x;
    const int wid = tid >> 5, lane = tid & 31;
    const int m0 = blockIdx.x * 128;
    const int n0 = blockIdx.y * 256;
    const int wm = wid & 3, wn = wid >> 2;

    float acc[2][16][4];
    #pragma unroll
    for (int a=0;a<2;a++)
        #pragma unroll
        for (int j=0;j<16;j++)
            #pragma unroll
            for (int x=0;x<4;x++) acc[a][j][x] = 0.f;

    const __half* gA = g_Ah + (size_t)m0*KA;
    const __half* gB = g_Bh + (size_t)n0*KA;

    auto load_stage = [&](int slot, int ks){
        int k0 = ks * 32;
        uint32_t sA = uA + slot*TSTA;
        uint32_t sB = uB + slot*TSTB;
        #pragma unroll
        for (int i = 0; i < 2; i++){
            int idx = tid + 256*i;
            int row = idx >> 2, lc = idx & 3;
            cpasync16(sA + row*80 + lc*16, gA + (size_t)row*KA + k0 + lc*8);
        }
        #pragma unroll
        for (int i = 0; i < 4; i++){
            int idx = tid + 256*i;
            int row = idx >> 2, lc = idx & 3;
            cpasync16(sB + row*80 + lc*16, gB + (size_t)row*KA + k0 + lc*8);
        }
        cp_commit();
    };

    load_stage(0, 0); load_stage(1, 1); load_stage(2, 2);

    const int g  = lane >> 3;
    const int lr = lane & 7;

    for (int ks = 0; ks < NKS; ks++){
        asm volatile("cp.async.wait_group 2;");
        __syncthreads();
        int ld = ks + NSTG - 1;
        if (ld < NKS) load_stage(ld & (NSTG-1), ld);
        else cp_commit();

        const uint32_t bufA = uA + (ks & (NSTG-1))*TSTA;
        const uint32_t bufB = uB + (ks & (NSTG-1))*TSTB;

        #pragma unroll
        for (int kk = 0; kk < 32; kk += 16){
            uint32_t afr[2][4];
            #pragma unroll
            for (int mi = 0; mi < 2; mi++){
                int row = wm*32 + mi*16 + ((g & 1) ? 8 : 0) + lr;
                int kof = kk + (g >> 1)*8;
                ldm4(afr[mi], bufA + row*80 + kof*2);
            }
            uint32_t bfr[8][4];
            #pragma unroll
            for (int p = 0; p < 8; p++){
                int row = wn*128 + p*16 + (g >> 1)*8 + lr;
                int kof = kk + (g & 1)*8;
                ldm4(bfr[p], bufB + row*80 + kof*2);
            }
            #pragma unroll
            for (int mi = 0; mi < 2; mi++)
                #pragma unroll
                for (int j = 0; j < 16; j++){
                    int p = j >> 1, h2 = (j & 1)*2;
                    mma16816h(acc[mi][j], afr[mi], bfr[p][h2], bfr[p][h2+1]);
                }
        }
        __syncthreads();
    }

    const int tm = lane >> 2;
    const int tn = (lane & 3)*2;
    #pragma unroll
    for (int mi = 0; mi < 2; mi++){
        #pragma unroll
        for (int j = 0; j < 16; j++){
            int gn = n0 + wn*128 + j*8 + tn;
            float2 bb = *(const float2*)(bias + gn);
            int gm0 = m0 + wm*32 + mi*16 + tm;
            if (gm0 < MPROJ){
                float2 o; o.x = acc[mi][j][0] + bb.x; o.y = acc[mi][j][1] + bb.y;
                *(float2*)(out + (size_t)gm0*VTS + gn) = o;
            }
            int gm1 = gm0 + 8;
            if (gm1 < MPROJ){
                float2 o; o.x = acc[mi][j][2] + bb.x; o.y = acc[mi][j][3] + bb.y;
                *(float2*)(out + (size_t)gm1*VTS + gn) = o;
            }
        }
    }
}

extern "C" void kernel_launch(void* const* d_in, const int* in_sizes, int n_in,
                              void* d_out, int out_size)
{
    const int*   src      = (const int*)  d_in[0];
    const int*   pos      = (const int*)  d_in[2];
    const int*   tgt      = (const int*)  d_in[3];
    const float* enc_emb  = (const float*)d_in[4];
    const float* pos_emb  = (const float*)d_in[5];
    const float* cat_W    = (const float*)d_in[6];
    const float* cat_b    = (const float*)d_in[7];
    const float* scale_W  = (const float*)d_in[8];
    const float* scale_b  = (const float*)d_in[9];
    const float* dec_emb  = (const float*)d_in[10];
    const float* attn_W   = (const float*)d_in[11];
    const float* W_ih     = (const float*)d_in[13];
    const float* W_hh     = (const float*)d_in[14];
    const float* b_ih     = (const float*)d_in[15];
    const float* b_hh     = (const float*)d_in[16];
    const float* proj_W   = (const float*)d_in[17];
    const float* proj_b   = (const float*)d_in[18];
    float* out = (float*)d_out;

    static cudaStream_t s2 = nullptr;
    static cudaEvent_t evFork = nullptr, evCat = nullptr, evWih = nullptr,
                       evWhh = nullptr, evW = nullptr;
    static bool init_done = false;
    if (!init_done){
        cudaFuncSetAttribute(proj_mma, cudaFuncAttributeMaxDynamicSharedMemorySize, SM_PROJ);
        cudaFuncSetAttribute(pre_mma, cudaFuncAttributeMaxDynamicSharedMemorySize, SM_PROJ);
        cudaFuncSetAttribute(enc_mma, cudaFuncAttributeMaxDynamicSharedMemorySize, SM_PROJ);
        cudaFuncSetAttribute(decoder_tc, cudaFuncAttributeMaxDynamicSharedMemorySize, DSM_TOT);
        cudaStreamCreateWithFlags(&s2, cudaStreamNonBlocking);
        cudaEventCreateWithFlags(&evFork, cudaEventDisableTiming);
        cudaEventCreateWithFlags(&evCat, cudaEventDisableTiming);
        cudaEventCreateWithFlags(&evWih, cudaEventDisableTiming);
        cudaEventCreateWithFlags(&evWhh, cudaEventDisableTiming);
        cudaEventCreateWithFlags(&evW, cudaEventDisableTiming);
        init_done = true;
    }

    int per_sm = 0, n_sm = 0;
    cudaOccupancyMaxActiveBlocksPerMultiprocessor(&per_sm, decoder_tc, 128, DSM_TOT);
    cudaDeviceGetAttribute(&n_sm, cudaDevAttrMultiProcessorCount, 0);
    const bool persistent_ok = ((long)per_sm * n_sm >= DCTA);

    // Fork: all weight conversions on the side stream
    cudaEventRecord(evFork, 0);
    cudaStreamWaitEvent(s2, evFork, 0);
    conv_catw<<<512, 256, 0, s2>>>(cat_W);
    cudaEventRecord(evCat, s2);
    conv_wih<<<4096, 256, 0, s2>>>(W_ih);
    cudaEventRecord(evWih, s2);
    conv_whh<<<4096, 256, 0, s2>>>(W_hh);
    cudaEventRecord(evWhh, s2);
    conv_w<<<32000, 256, 0, s2>>>(proj_W);
    cudaEventRecord(evW, s2);

    // Main chain: encoder (fp16 tensor cores)
    build_aenc<<<3200, 256>>>(src, pos, enc_emb, pos_emb);
    cudaStreamWaitEvent(0, evCat, 0);
    enc_mma<<<dim3(25,2), 256, SM_PROJ>>>(cat_b);
    avg_kernel<<<64, 512>>>();
    h0_kernel<<<8192, 256>>>(scale_W, scale_b);

    // Loop-invariant attention context + fused fp16 pre-GEMM
    attn_kernel<<<64, 256>>>(attn_W, src);
    build_apre<<<3200, 256>>>(tgt, dec_emb);
    cudaStreamWaitEvent(0, evWih, 0);
    pre_mma<<<dim3(25,16), 256, SM_PROJ>>>(b_ih, b_hh);

    // Recurrence: persistent tensor-core decoder (distributed flag barrier)
    cudaStreamWaitEvent(0, evWhh, 0);
    if (persistent_ok){
        decoder_tc<<<DCTA, 128, DSM_TOT>>>();
    } else {
        for (int t = 0; t < NSTEP; t++){
            gates_gemm<<<dim3(32, KSPLIT), 128>>>(W_hh);
            lstm_pw<<<256, 256>>>(t);
        }
    }

    // fp16 tensor-core projection (waits for proj_W conversion)
    cudaStreamWaitEvent(0, evW, 0);
    proj_mma<<<dim3(25,125), 256, SM_PROJ>>>(out, proj_b);
}